// round 16
// baseline (speedup 1.0000x reference)
#include <cuda_runtime.h>
#include <cuda_bf16.h>
#include <stdint.h>
#include <math.h>

// Problem constants
#define D       512
#define NQKV    1536
#define MV      16384       // unique v-token rows (B*S*16)
#define MTOK    16448       // + 64 a-token rows
#define MTOKPAD 16512       // padded to tile multiple
#define MA16    16384       // a-row attention outputs (bs*16 + tt)

// Output layout offsets (floats)
#define OFF1    4194304     // vf_o
#define OFF2    8388608     // ap_o
#define OFF3    8404992     // af_o

// Scratch
__device__ __nv_bfloat16 g_tok_hi[(size_t)MTOKPAD * D];
__device__ __nv_bfloat16 g_tok_lo[(size_t)MTOKPAD * D];
__device__ __nv_bfloat16 g_wq_hi[(size_t)D * NQKV];
__device__ __nv_bfloat16 g_wq_lo[(size_t)D * NQKV];
__device__ __nv_bfloat16 g_wp_hi[(size_t)D * D];
__device__ __nv_bfloat16 g_wp_lo[(size_t)D * D];
// QKV outputs: RoPE'd Q/K and V, bf16 hi/lo
__device__ __nv_bfloat16 g_q_hi[(size_t)MTOK * D];
__device__ __nv_bfloat16 g_q_lo[(size_t)MTOK * D];
__device__ __nv_bfloat16 g_k_hi[(size_t)MTOK * D];
__device__ __nv_bfloat16 g_k_lo[(size_t)MTOK * D];
__device__ __nv_bfloat16 g_v_hi[(size_t)MTOK * D];
__device__ __nv_bfloat16 g_v_lo[(size_t)MTOK * D];
__device__ __nv_bfloat16 g_o2_hi[(size_t)MTOKPAD * D];   // proj input
__device__ __nv_bfloat16 g_o2_lo[(size_t)MTOKPAD * D];
__device__ float         g_oa[(size_t)MA16 * D];         // a-row attn outputs (fp32)
__device__ float         g_am[64 * D];                   // a-row mean staging
__device__ float2        g_rope[1024];   // (sin, cos) for t*32+j

// ---------------------------------------------------------------------------
__device__ __forceinline__ uint32_t smem_u32(const void* p) {
    return (uint32_t)__cvta_generic_to_shared(p);
}

#define LDSM_X4(r0,r1,r2,r3,addr) \
    asm volatile("ldmatrix.sync.aligned.m8n8.x4.shared.b16 {%0,%1,%2,%3}, [%4];" \
        : "=r"(r0),"=r"(r1),"=r"(r2),"=r"(r3) : "r"(addr))

#define LDSM_X4_T(r0,r1,r2,r3,addr) \
    asm volatile("ldmatrix.sync.aligned.m8n8.x4.trans.shared.b16 {%0,%1,%2,%3}, [%4];" \
        : "=r"(r0),"=r"(r1),"=r"(r2),"=r"(r3) : "r"(addr))

#define MMA16816(d, a, b) \
    asm volatile("mma.sync.aligned.m16n8k16.row.col.f32.bf16.bf16.f32 " \
        "{%0,%1,%2,%3},{%4,%5,%6,%7},{%8,%9},{%0,%1,%2,%3};" \
        : "+f"(d[0]),"+f"(d[1]),"+f"(d[2]),"+f"(d[3]) \
        : "r"(a[0]),"r"(a[1]),"r"(a[2]),"r"(a[3]),"r"(b[0]),"r"(b[1]))

#define CP16(dst, src) \
    asm volatile("cp.async.cg.shared.global [%0], [%1], 16;" :: "r"(dst), "l"(src))
#define CP_COMMIT() asm volatile("cp.async.commit_group;")
#define CP_WAIT(n)  asm volatile("cp.async.wait_group %0;" :: "n"(n))

__device__ __forceinline__ void cvt_hilo(float x, __nv_bfloat16& h, __nv_bfloat16& l) {
    h = __float2bfloat16(x);
    l = __float2bfloat16(x - __bfloat162float(h));
}

// Token row gather: mode 0 = v-tokens, mode 1 = a-tokens
__device__ __forceinline__ const float* token_ptr(int r, int mode,
    const float* __restrict__ p0, const float* __restrict__ p1)
{
    if (mode == 0) {
        int b = r >> 12;
        int rem = r & 4095;
        int s = rem >> 4;
        int t = rem & 15;
        if (t < 8)  return p0 + ((size_t)((((b << 3) + t) << 8) + s) << 9);
        else        return p1 + ((size_t)((((b << 3) + (t - 8)) << 8) + s) << 9);
    } else {
        int b = r >> 4;
        int t = r & 15;
        if (t < 8)  return p0 + ((size_t)((b << 3) + t) << 9);
        else        return p1 + ((size_t)((b << 3) + (t - 8)) << 9);
    }
}

// ---------------------------------------------------------------------------
// Pre-conversion kernels
// ---------------------------------------------------------------------------
__global__ void __launch_bounds__(256) conv_tokens(
    const float* __restrict__ v_p, const float* __restrict__ v_f,
    const float* __restrict__ a_p, const float* __restrict__ a_f)
{
    int idx = blockIdx.x * 256 + threadIdx.x;    // one float4 per thread
    int row = idx >> 7;
    int c4  = (idx & 127) << 2;
    if (row >= MTOK) return;
    const float* src = (row < MV) ? token_ptr(row, 0, v_p, v_f)
                                  : token_ptr(row - MV, 1, a_p, a_f);
    float4 v = *(const float4*)(src + c4);
    __nv_bfloat16 h[4], l[4];
    cvt_hilo(v.x, h[0], l[0]); cvt_hilo(v.y, h[1], l[1]);
    cvt_hilo(v.z, h[2], l[2]); cvt_hilo(v.w, h[3], l[3]);
    size_t off = (size_t)row * D + c4;
    *(__nv_bfloat162*)(g_tok_hi + off)     = __nv_bfloat162(h[0], h[1]);
    *(__nv_bfloat162*)(g_tok_hi + off + 2) = __nv_bfloat162(h[2], h[3]);
    *(__nv_bfloat162*)(g_tok_lo + off)     = __nv_bfloat162(l[0], l[1]);
    *(__nv_bfloat162*)(g_tok_lo + off + 2) = __nv_bfloat162(l[2], l[3]);
}

__global__ void __launch_bounds__(256) conv_weights(
    const float* __restrict__ Wq, const float* __restrict__ Wp)
{
    int idx = blockIdx.x * 256 + threadIdx.x;    // one float4 per thread
    const int NQ4 = (D * NQKV) / 4;              // 196608
    const float* src;
    __nv_bfloat16 *dh, *dl;
    size_t off;
    if (idx < NQ4)      { src = Wq; dh = g_wq_hi; dl = g_wq_lo; off = (size_t)idx << 2; }
    else                { idx -= NQ4;
                          if (idx >= (D * D) / 4) return;
                          src = Wp; dh = g_wp_hi; dl = g_wp_lo; off = (size_t)idx << 2; }
    float4 v = *(const float4*)(src + off);
    __nv_bfloat16 h[4], l[4];
    cvt_hilo(v.x, h[0], l[0]); cvt_hilo(v.y, h[1], l[1]);
    cvt_hilo(v.z, h[2], l[2]); cvt_hilo(v.w, h[3], l[3]);
    *(__nv_bfloat162*)(dh + off)     = __nv_bfloat162(h[0], h[1]);
    *(__nv_bfloat162*)(dh + off + 2) = __nv_bfloat162(h[2], h[3]);
    *(__nv_bfloat162*)(dl + off)     = __nv_bfloat162(l[0], l[1]);
    *(__nv_bfloat162*)(dl + off + 2) = __nv_bfloat162(l[2], l[3]);
}

// RoPE sin/cos table + zero the a-mean staging
__global__ void rope_table_kernel(void)
{
    int idx = threadIdx.x + blockIdx.x * 256;
    if (idx < 1024) {
        int t = idx >> 5;
        int j = idx & 31;
        float inv = exp2f(-0.41524101186091903f * (float)j);
        float ang = (float)t * inv;
        float sn, cs;
        sincosf(ang, &sn, &cs);
        g_rope[idx] = make_float2(sn, cs);
    }
    if (idx < 64 * D) g_am[idx] = 0.f;
}

// ---------------------------------------------------------------------------
// Pipelined bf16x3 GEMM: 128x128 tile, BK=32, 2-stage cp.async, 256 threads.
// ---------------------------------------------------------------------------
#define STG_A_HI   0
#define STG_A_LO   10240
#define STG_B_HI   20480
#define STG_B_LO   29184
#define STG_STRIDE 37888
#define SMEM_BYTES (2 * STG_STRIDE)
#define NSLAB      16

__device__ __forceinline__ void prefetch_slab(
    uint32_t stg,
    const __nv_bfloat16* __restrict__ Ahi, const __nv_bfloat16* __restrict__ Alo,
    const __nv_bfloat16* __restrict__ Bhi, const __nv_bfloat16* __restrict__ Blo,
    int ldb, int bn, int k0, int tid)
{
    #pragma unroll
    for (int t = 0; t < 2; ++t) {
        int q  = tid + (t << 8);              // 0..511
        int r  = q >> 2, kc = (q & 3) << 3;   // A: 128 rows x 4 chunks
        uint32_t ao = (uint32_t)(r * 80 + (kc << 1));
        size_t asrc = (size_t)r * D + k0 + kc;
        CP16(stg + STG_A_HI + ao, Ahi + asrc);
        CP16(stg + STG_A_LO + ao, Alo + asrc);
        int br = q >> 4, nc = (q & 15) << 3;  // B: 32 rows x 16 chunks
        uint32_t bo = (uint32_t)(br * 272 + (nc << 1));
        size_t bsrc = (size_t)(k0 + br) * ldb + bn + nc;
        CP16(stg + STG_B_HI + bo, Bhi + bsrc);
        CP16(stg + STG_B_LO + bo, Blo + bsrc);
    }
}

__device__ __forceinline__ void compute_slab(
    char* stg, int m0, int n0, int lane, float (&acc)[2][8][4])
{
    uint32_t ah[2][4], al[2][4], bh[8][2], bl[8][2];
    #pragma unroll
    for (int ks = 0; ks < 2; ++ks) {
        const int k0   = ks << 4;
        const int arow = lane & 15;
        const int acol = k0 + ((lane >> 4) << 3);
        #pragma unroll
        for (int mt = 0; mt < 2; ++mt) {
            uint32_t ad = smem_u32(stg + STG_A_HI + (m0 + (mt << 4) + arow) * 80 + acol * 2);
            LDSM_X4(ah[mt][0], ah[mt][1], ah[mt][2], ah[mt][3], ad);
            uint32_t ad2 = smem_u32(stg + STG_A_LO + (m0 + (mt << 4) + arow) * 80 + acol * 2);
            LDSM_X4(al[mt][0], al[mt][1], al[mt][2], al[mt][3], ad2);
        }
        #pragma unroll
        for (int p = 0; p < 4; ++p) {
            const int ncol = n0 + (p << 4) + ((lane >> 4) << 3);
            uint32_t bd = smem_u32(stg + STG_B_HI + (k0 + (lane & 15)) * 272 + ncol * 2);
            LDSM_X4_T(bh[2*p][0], bh[2*p][1], bh[2*p+1][0], bh[2*p+1][1], bd);
            uint32_t bd2 = smem_u32(stg + STG_B_LO + (k0 + (lane & 15)) * 272 + ncol * 2);
            LDSM_X4_T(bl[2*p][0], bl[2*p][1], bl[2*p+1][0], bl[2*p+1][1], bd2);
        }
        #pragma unroll
        for (int mt = 0; mt < 2; ++mt)
            #pragma unroll
            for (int nt = 0; nt < 8; ++nt) {
                MMA16816(acc[mt][nt], ah[mt], bh[nt]);
                MMA16816(acc[mt][nt], ah[mt], bl[nt]);
                MMA16816(acc[mt][nt], al[mt], bh[nt]);
            }
    }
}

#define GEMM_MAIN(AHI, ALO, BHI, BLO, LDB, BN)                                   \
    extern __shared__ char smem[];                                               \
    const uint32_t sbase = smem_u32(smem);                                       \
    const int tid  = threadIdx.x;                                                \
    const int lane = tid & 31;                                                   \
    const int w    = tid >> 5;                                                   \
    const int m0   = (w >> 1) << 5;                                              \
    const int n0   = (w & 1) << 6;                                               \
    float acc[2][8][4];                                                          \
    _Pragma("unroll")                                                            \
    for (int mt = 0; mt < 2; ++mt)                                               \
        _Pragma("unroll")                                                        \
        for (int nt = 0; nt < 8; ++nt)                                           \
            _Pragma("unroll")                                                    \
            for (int e = 0; e < 4; ++e) acc[mt][nt][e] = 0.f;                    \
    prefetch_slab(sbase, AHI, ALO, BHI, BLO, LDB, BN, 0, tid);                   \
    CP_COMMIT();                                                                 \
    for (int ks = 0; ks < NSLAB; ++ks) {                                         \
        if (ks + 1 < NSLAB) {                                                    \
            prefetch_slab(sbase + ((ks + 1) & 1) * STG_STRIDE,                   \
                          AHI, ALO, BHI, BLO, LDB, BN, (ks + 1) * 32, tid);      \
            CP_COMMIT();                                                         \
            CP_WAIT(1);                                                          \
        } else {                                                                 \
            CP_WAIT(0);                                                          \
        }                                                                        \
        __syncthreads();                                                         \
        compute_slab(smem + (ks & 1) * STG_STRIDE, m0, n0, lane, acc);           \
        __syncthreads();                                                         \
    }

// ---------------------------------------------------------------------------
// QKV GEMM with fused RoPE + bf16 hi/lo split epilogue.
// ---------------------------------------------------------------------------
__global__ void __launch_bounds__(256) qkv_gemm(void)
{
    const int bm = blockIdx.y << 7;
    const int bn = blockIdx.x << 7;
    GEMM_MAIN(g_tok_hi + (size_t)bm * D, g_tok_lo + (size_t)bm * D,
              g_wq_hi, g_wq_lo, NQKV, bn)

    const int cw     = bn + n0;            // 64-aligned global col window
    const int region = cw >> 9;            // 0=Q, 1=K, 2=V
    __nv_bfloat16 *dh, *dl;
    if (region == 0)      { dh = g_q_hi; dl = g_q_lo; }
    else if (region == 1) { dh = g_k_hi; dl = g_k_lo; }
    else                  { dh = g_v_hi; dl = g_v_lo; }
    const int cbase = cw & 511;

    #pragma unroll
    for (int mt = 0; mt < 2; ++mt) {
        int rA   = bm + m0 + (mt << 4) + (lane >> 2);
        int posA = (rA & 15) + ((rA >= MV) ? 16 : 0);
        if (region < 2) {
            #pragma unroll
            for (int nt = 0; nt < 4; ++nt) {
                #pragma unroll
                for (int je = 0; je < 2; ++je) {
                    int j = (nt << 3) + ((lane & 3) << 1) + je;
                    float2 scA = g_rope[(posA << 5) + j];
                    float2 scB = g_rope[((posA + 8) << 5) + j];
                    float x1 = acc[mt][nt][je],   x2 = acc[mt][nt+4][je];
                    acc[mt][nt][je]     = x1 * scA.y - x2 * scA.x;
                    acc[mt][nt+4][je]   = x2 * scA.y + x1 * scA.x;
                    float y1 = acc[mt][nt][je+2], y2 = acc[mt][nt+4][je+2];
                    acc[mt][nt][je+2]   = y1 * scB.y - y2 * scB.x;
                    acc[mt][nt+4][je+2] = y2 * scB.y + y1 * scB.x;
                }
            }
        }
        #pragma unroll
        for (int nt = 0; nt < 8; ++nt) {
            int c = cbase + (nt << 3) + ((lane & 3) << 1);
            if (rA < MTOK) {
                __nv_bfloat16 h0,l0,h1,l1;
                cvt_hilo(acc[mt][nt][0], h0, l0);
                cvt_hilo(acc[mt][nt][1], h1, l1);
                *(__nv_bfloat162*)(dh + (size_t)rA * D + c) = __nv_bfloat162(h0, h1);
                *(__nv_bfloat162*)(dl + (size_t)rA * D + c) = __nv_bfloat162(l0, l1);
            }
            if (rA + 8 < MTOK) {
                __nv_bfloat16 h2,l2,h3,l3;
                cvt_hilo(acc[mt][nt][2], h2, l2);
                cvt_hilo(acc[mt][nt][3], h3, l3);
                *(__nv_bfloat162*)(dh + (size_t)(rA + 8) * D + c) = __nv_bfloat162(h2, h3);
                *(__nv_bfloat162*)(dl + (size_t)(rA + 8) * D + c) = __nv_bfloat162(l2, l3);
            }
        }
    }
}

// ---------------------------------------------------------------------------
// Proj GEMM: g_o2[16448,512] @ W_proj[512,512] + bias, scatter (NO atomics).
// ---------------------------------------------------------------------------
__device__ __forceinline__ void scatter2(float* __restrict__ out, int r, int c, float v)
{
    if (r < MV) {
        int bs = r >> 4, t = r & 15, b = bs >> 8, s = bs & 255;
        if (t < 8)
            out[((size_t)((((b << 3) + t) << 8) + s) << 9) + c] = v;
        else
            out[OFF1 + ((size_t)((((b << 3) + (t - 8)) << 8) + s) << 9) + c] = v;
    } else if (r < MTOK) {
        int j = r - MV;
        int b = j >> 4, tt = j & 15;
        if (tt < 8)
            out[OFF2 + (((b << 3) + tt) << 9) + c] = v;
        else
            out[OFF3 + (((b << 3) + (tt - 8)) << 9) + c] = v;
    }
}

__global__ void __launch_bounds__(256) proj_gemm(
    const float* __restrict__ bias, float* __restrict__ out)
{
    const int bm = blockIdx.y << 7;
    const int bn = blockIdx.x << 7;
    GEMM_MAIN(g_o2_hi + (size_t)bm * D, g_o2_lo + (size_t)bm * D,
              g_wp_hi, g_wp_lo, D, bn)

    #pragma unroll
    for (int mt = 0; mt < 2; ++mt) {
        int r0 = bm + m0 + (mt << 4) + (lane >> 2);
        #pragma unroll
        for (int nt = 0; nt < 8; ++nt) {
            int c = bn + n0 + (nt << 3) + ((lane & 3) << 1);
            float b0 = bias[c], b1 = bias[c + 1];
            scatter2(out, r0,     c,     acc[mt][nt][0] + b0);
            scatter2(out, r0,     c + 1, acc[mt][nt][1] + b1);
            scatter2(out, r0 + 8, c,     acc[mt][nt][2] + b0);
            scatter2(out, r0 + 8, c + 1, acc[mt][nt][3] + b1);
        }
    }
}

// ---------------------------------------------------------------------------
// a-row mean: partials (grid 64 x 8, 32 s each) -> fp32 atomics -> finalize
// ---------------------------------------------------------------------------
__global__ void __launch_bounds__(256) reduce_a(void)
{
    int j  = blockIdx.x;            // 0..63 = b*16+tt
    int sq = blockIdx.y;            // 0..7
    int c2 = threadIdx.x << 1;
    int b  = j >> 4;
    int tt = j & 15;
    float s0 = 0.f, s1 = 0.f;
    int sbase = sq << 5;
    #pragma unroll 4
    for (int s = 0; s < 32; ++s) {
        const float* row = g_oa + (size_t)((((b << 8) + sbase + s) << 4) + tt) * D + c2;
        float2 v = *(const float2*)row;
        s0 += v.x; s1 += v.y;
    }
    atomicAdd(&g_am[j * D + c2],     s0 * (1.f / 256.f));
    atomicAdd(&g_am[j * D + c2 + 1], s1 * (1.f / 256.f));
}

__global__ void __launch_bounds__(256) conv_am(void)
{
    int j  = blockIdx.x;
    int c2 = threadIdx.x << 1;
    float2 v = *(const float2*)(g_am + j * D + c2);
    __nv_bfloat16 h0, l0, h1, l1;
    cvt_hilo(v.x, h0, l0);
    cvt_hilo(v.y, h1, l1);
    size_t off = (size_t)(MV + j) * D + c2;
    *(__nv_bfloat162*)(g_o2_hi + off) = __nv_bfloat162(h0, h1);
    *(__nv_bfloat162*)(g_o2_lo + off) = __nv_bfloat162(l0, l1);
}

// ---------------------------------------------------------------------------
// Attention (tensor-core, pure-copy staging, K row-major / non-trans B):
// one block per (bs, head), 128 threads.
// Smem: QH/QL [32][72] @ 0/4608; KH/KL [32][72] @ 9216/13824;
//       VH/VL [32][72] @ 18432/23040; PH/PL [32][40] @ 27648/30208;
//       Ss [32][33] f32 @ 32768. Total 36992.
// ---------------------------------------------------------------------------
#define A_QH  0
#define A_QL  4608
#define A_KH  9216
#define A_KL  13824
#define A_VH  18432
#define A_VL  23040
#define A_PH  27648
#define A_PL  30208
#define A_SS  32768
#define ATT_SMEM 36992

__global__ void __launch_bounds__(128) attn_kernel()
{
    extern __shared__ char asm_[];
    __nv_bfloat16* QH = (__nv_bfloat16*)(asm_ + A_QH);   // [32][72]
    __nv_bfloat16* QL = (__nv_bfloat16*)(asm_ + A_QL);
    __nv_bfloat16* KH = (__nv_bfloat16*)(asm_ + A_KH);   // [32][72] row-major
    __nv_bfloat16* KL = (__nv_bfloat16*)(asm_ + A_KL);
    __nv_bfloat16* VH = (__nv_bfloat16*)(asm_ + A_VH);   // [32][72]
    __nv_bfloat16* VL = (__nv_bfloat16*)(asm_ + A_VL);
    __nv_bfloat16* PH = (__nv_bfloat16*)(asm_ + A_PH);   // [32][40]
    __nv_bfloat16* PL = (__nv_bfloat16*)(asm_ + A_PL);
    float* Ss = (float*)(asm_ + A_SS);                   // [32][33]

    const int tid  = threadIdx.x;
    const int lane = tid & 31;
    const int w    = tid >> 5;
    const int bh   = blockIdx.x;
    const int bs   = bh >> 3;
    const int h    = bh & 7;
    const int b    = bs >> 8;

    // Phase 1: pure vector copy staging (Q/K/V all row-major 16B stores)
    #pragma unroll
    for (int p = 0; p < 2; ++p) {
        int idx = tid + (p << 7);         // 0..255
        int t   = idx >> 3;               // 0..31 row
        int c8  = (idx & 7) << 3;         // 0,8,..,56
        int row = (t < 16) ? ((bs << 4) + t) : (MV + (b << 4) + (t - 16));
        size_t src = (size_t)row * D + (h << 6) + c8;
        *(uint4*)(QH + t*72 + c8) = *(const uint4*)(g_q_hi + src);
        *(uint4*)(QL + t*72 + c8) = *(const uint4*)(g_q_lo + src);
        *(uint4*)(KH + t*72 + c8) = *(const uint4*)(g_k_hi + src);
        *(uint4*)(KL + t*72 + c8) = *(const uint4*)(g_k_lo + src);
        *(uint4*)(VH + t*72 + c8) = *(const uint4*)(g_v_hi + src);
        *(uint4*)(VL + t*72 + c8) = *(const uint4*)(g_v_lo + src);
    }
    __syncthreads();

    // Phase 2: S = QK^T * scale via MMA. B = K[n][k] row-major, non-trans LDSM.
    {
        const int m0 = (w & 1) << 4;
        const int n0 = (w >> 1) << 4;
        float sacc[2][4] = {{0.f,0.f,0.f,0.f},{0.f,0.f,0.f,0.f}};
        uint32_t ah[4], al[4];
        uint32_t kr[4], kr2[4];
        #pragma unroll
        for (int kc = 0; kc < 4; ++kc) {
            const int k0 = kc << 4;
            const int arow = m0 + (lane & 15);
            const int acol = k0 + ((lane >> 4) << 3);
            LDSM_X4(ah[0], ah[1], ah[2], ah[3], smem_u32(QH + arow*72 + acol));
            LDSM_X4(al[0], al[1], al[2], al[3], smem_u32(QL + arow*72 + acol));
            const int nrow = n0 + (lane & 15);
            const int kcol = k0 + ((lane >> 4) << 3);
            LDSM_X4(kr[0], kr[1], kr[2], kr[3], smem_u32(KH + nrow*72 + kcol));
            LDSM_X4(kr2[0], kr2[1], kr2[2], kr2[3], smem_u32(KL + nrow*72 + kcol));
            // fragments: n-half 0 -> {r0, r2}, n-half 1 -> {r1, r3}
            uint32_t bh0[2] = {kr[0],  kr[2]};
            uint32_t bh1[2] = {kr[1],  kr[3]};
            uint32_t bl0[2] = {kr2[0], kr2[2]};
            uint32_t bl1[2] = {kr2[1], kr2[3]};
            MMA16816(sacc[0], ah, bh0);
            MMA16816(sacc[0], ah, bl0);
            MMA16816(sacc[0], al, bh0);
            MMA16816(sacc[1], ah, bh1);
            MMA16816(sacc[1], ah, bl1);
            MMA16816(sacc[1], al, bh1);
        }
        const int r0 = m0 + (lane >> 2);
        #pragma unroll
        for (int nt = 0; nt < 2; ++nt) {
            int c = n0 + (nt << 3) + ((lane & 3) << 1);
            Ss[r0*33 + c]       = sacc[nt][0] * 0.125f;
            Ss[r0*33 + c + 1]   = sacc[nt][1] * 0.125f;
            Ss[(r0+8)*33 + c]     = sacc[nt][2] * 0.125f;
            Ss[(r0+8)*33 + c + 1] = sacc[nt][3] * 0.125f;
        }
    }
    __syncthreads();

    // Phase 3: row softmax; emit P as bf16 hi/lo directly
    #pragma unroll
    for (int rr = 0; rr < 8; ++rr) {
        int i = (w << 3) + rr;
        float val = Ss[i*33 + lane];
        float m = val;
        #pragma unroll
        for (int o = 16; o > 0; o >>= 1) m = fmaxf(m, __shfl_xor_sync(0xffffffffu, m, o));
        float e = expf(val - m);
        float sum = e;
        #pragma unroll
        for (int o = 16; o > 0; o >>= 1) sum += __shfl_xor_sync(0xffffffffu, sum, o);
        float pv = e / sum;
        __nv_bfloat16 hh, ll;
        cvt_hilo(pv, hh, ll);
        PH[i*40 + lane] = hh;
        PL[i*40 + lane] = ll;
    }
    __syncthreads();

    // Phase 4: O = P @ V via MMA. V row-major [k][n] -> trans LDSM (as before).
    {
        const int m0 = (w & 1) << 4;
        const int n0 = (w >> 1) << 5;
        float oacc[4][4];
        #pragma unroll
        for (int nt = 0; nt < 4; ++nt)
            #pragma unroll
            for (int e = 0; e < 4; ++e) oacc[nt][e] = 0.f;
        uint32_t ah[4], al[4], bhf[4][2], blf[4][2];
        #pragma unroll
        for (int kc = 0; kc < 2; ++kc) {
            const int k0 = kc << 4;
            const int arow = m0 + (lane & 15);
            const int acol = k0 + ((lane >> 4) << 3);
            LDSM_X4(ah[0], ah[1], ah[2], ah[3], smem_u32(PH + arow*40 + acol));
            LDSM_X4(al[0], al[1], al[2], al[3], smem_u32(PL + arow*40 + acol));
            #pragma unroll
            for (int p = 0; p < 2; ++p) {
                const int brow = k0 + (lane & 15);
                const int bcol = n0 + (p << 4) + ((lane >> 4) << 3);
                LDSM_X4_T(bhf[2*p][0], bhf[2*p][1], bhf[2*p+1][0], bhf[2*p+1][1],
                          smem_u32(VH + brow*72 + bcol));
                LDSM_X4_T(blf[2*p][0], blf[2*p][1], blf[2*p+1][0], blf[2*p+1][1],
                          smem_u32(VL + brow*72 + bcol));
            }
            #pragma unroll
            for (int nt = 0; nt < 4; ++nt) {
                MMA16816(oacc[nt], ah, bhf[nt]);
                MMA16816(oacc[nt], ah, blf[nt]);
                MMA16816(oacc[nt], al, bhf[nt]);
            }
        }
        // Epilogue: m0==0 -> v rows (bf16 hi/lo to g_o2); m0==16 -> a rows (fp32)
        const int r0 = m0 + (lane >> 2);
        if (m0 == 0) {
            #pragma unroll
            for (int nt = 0; nt < 4; ++nt) {
                int c = n0 + (nt << 3) + ((lane & 3) << 1);
                size_t o0 = (size_t)((bs << 4) + r0) * D + (h << 6) + c;
                size_t o1 = (size_t)((bs << 4) + r0 + 8) * D + (h << 6) + c;
                __nv_bfloat16 h0,l0,h1,l1,h2,l2,h3,l3;
                cvt_hilo(oacc[nt][0], h0, l0); cvt_hilo(oacc[nt][1], h1, l1);
                cvt_hilo(oacc[nt][2], h2, l2); cvt_hilo(oacc[nt][3], h3, l3);
                *(__nv_bfloat162*)(g_o2_hi + o0) = __nv_bfloat162(h0, h1);
                *(__nv_bfloat162*)(g_o2_lo + o0) = __nv_bfloat162(l0, l1);
                *(__nv_bfloat162*)(g_o2_hi + o1) = __nv_bfloat162(h2, h3);
                *(__nv_bfloat162*)(g_o2_lo + o1) = __nv_bfloat162(l2, l3);
            }
        } else {
            int ra = r0 - 16;                 // 0..7
            #pragma unroll
            for (int nt = 0; nt < 4; ++nt) {
                int c = n0 + (nt << 3) + ((lane & 3) << 1);
                size_t o0 = (size_t)((bs << 4) + ra) * D + (h << 6) + c;
                size_t o1 = (size_t)((bs << 4) + ra + 8) * D + (h << 6) + c;
                *(float2*)(g_oa + o0) = make_float2(oacc[nt][0], oacc[nt][1]);
                *(float2*)(g_oa + o1) = make_float2(oacc[nt][2], oacc[nt][3]);
            }
        }
    }
}

// ---------------------------------------------------------------------------
extern "C" void kernel_launch(void* const* d_in, const int* in_sizes, int n_in,
                              void* d_out, int out_size)
{
    const float* v_p    = (const float*)d_in[0];
    const float* v_f    = (const float*)d_in[1];
    const float* a_p    = (const float*)d_in[2];
    const float* a_f    = (const float*)d_in[3];
    const float* W_qkv  = (const float*)d_in[4];
    const float* W_proj = (const float*)d_in[5];
    const float* b_proj = (const float*)d_in[6];
    float* out = (float*)d_out;

    cudaFuncSetAttribute(qkv_gemm,  cudaFuncAttributeMaxDynamicSharedMemorySize, SMEM_BYTES);
    cudaFuncSetAttribute(proj_gemm, cudaFuncAttributeMaxDynamicSharedMemorySize, SMEM_BYTES);
    cudaFuncSetAttribute(attn_kernel, cudaFuncAttributeMaxDynamicSharedMemorySize, ATT_SMEM);

    rope_table_kernel<<<128, 256>>>();       // rope table + zero g_am
    conv_weights<<<1024, 256>>>(W_qkv, W_proj);
    conv_tokens<<<8224, 256>>>(v_p, v_f, a_p, a_f);

    qkv_gemm<<<dim3(12, 129), 256, SMEM_BYTES>>>();

    attn_kernel<<<8192, 128, ATT_SMEM>>>();

    reduce_a<<<dim3(64, 8), 256>>>();
    conv_am<<<64, 256>>>();

    proj_gemm<<<dim3(4, 129), 256, SMEM_BYTES>>>(b_proj, out);
}

// round 17
// speedup vs baseline: 1.2047x; 1.2047x over previous
#include <cuda_runtime.h>
#include <cuda_bf16.h>
#include <stdint.h>
#include <math.h>

// Problem constants
#define D       512
#define NQKV    1536
#define MV      16384       // unique v-token rows (B*S*16)
#define MTOK    16448       // + 64 a-token rows
#define MTOKPAD 16512       // padded to tile multiple
#define MA16    16384       // a-row attention outputs (bs*16 + tt)

// Output layout offsets (floats)
#define OFF1    4194304     // vf_o
#define OFF2    8388608     // ap_o
#define OFF3    8404992     // af_o

// Scratch
__device__ __nv_bfloat16 g_tok_hi[(size_t)MTOKPAD * D];
__device__ __nv_bfloat16 g_tok_lo[(size_t)MTOKPAD * D];
__device__ __nv_bfloat16 g_wq_hi[(size_t)D * NQKV];
__device__ __nv_bfloat16 g_wq_lo[(size_t)D * NQKV];
__device__ __nv_bfloat16 g_wp_hi[(size_t)D * D];
__device__ __nv_bfloat16 g_wp_lo[(size_t)D * D];
// QKV outputs: RoPE'd Q/K and V, bf16 hi/lo
__device__ __nv_bfloat16 g_q_hi[(size_t)MTOK * D];
__device__ __nv_bfloat16 g_q_lo[(size_t)MTOK * D];
__device__ __nv_bfloat16 g_k_hi[(size_t)MTOK * D];
__device__ __nv_bfloat16 g_k_lo[(size_t)MTOK * D];
__device__ __nv_bfloat16 g_v_hi[(size_t)MTOK * D];
__device__ __nv_bfloat16 g_v_lo[(size_t)MTOK * D];
__device__ __nv_bfloat16 g_o2_hi[(size_t)MTOKPAD * D];   // proj input
__device__ __nv_bfloat16 g_o2_lo[(size_t)MTOKPAD * D];
__device__ float         g_oa[(size_t)MA16 * D];         // a-row attn outputs (fp32)
__device__ float         g_am[64 * D];                   // a-row mean staging
__device__ float2        g_rope[1024];   // (sin, cos) for t*32+j

// ---------------------------------------------------------------------------
__device__ __forceinline__ uint32_t smem_u32(const void* p) {
    return (uint32_t)__cvta_generic_to_shared(p);
}

#define LDSM_X4(r0,r1,r2,r3,addr) \
    asm volatile("ldmatrix.sync.aligned.m8n8.x4.shared.b16 {%0,%1,%2,%3}, [%4];" \
        : "=r"(r0),"=r"(r1),"=r"(r2),"=r"(r3) : "r"(addr))

#define LDSM_X4_T(r0,r1,r2,r3,addr) \
    asm volatile("ldmatrix.sync.aligned.m8n8.x4.trans.shared.b16 {%0,%1,%2,%3}, [%4];" \
        : "=r"(r0),"=r"(r1),"=r"(r2),"=r"(r3) : "r"(addr))

#define MMA16816(d, a, b) \
    asm volatile("mma.sync.aligned.m16n8k16.row.col.f32.bf16.bf16.f32 " \
        "{%0,%1,%2,%3},{%4,%5,%6,%7},{%8,%9},{%0,%1,%2,%3};" \
        : "+f"(d[0]),"+f"(d[1]),"+f"(d[2]),"+f"(d[3]) \
        : "r"(a[0]),"r"(a[1]),"r"(a[2]),"r"(a[3]),"r"(b[0]),"r"(b[1]))

#define CP16(dst, src) \
    asm volatile("cp.async.cg.shared.global [%0], [%1], 16;" :: "r"(dst), "l"(src))
#define CP_COMMIT() asm volatile("cp.async.commit_group;")
#define CP_WAIT(n)  asm volatile("cp.async.wait_group %0;" :: "n"(n))

__device__ __forceinline__ void cvt_hilo(float x, __nv_bfloat16& h, __nv_bfloat16& l) {
    h = __float2bfloat16(x);
    l = __float2bfloat16(x - __bfloat162float(h));
}

// Token row gather: mode 0 = v-tokens, mode 1 = a-tokens
__device__ __forceinline__ const float* token_ptr(int r, int mode,
    const float* __restrict__ p0, const float* __restrict__ p1)
{
    if (mode == 0) {
        int b = r >> 12;
        int rem = r & 4095;
        int s = rem >> 4;
        int t = rem & 15;
        if (t < 8)  return p0 + ((size_t)((((b << 3) + t) << 8) + s) << 9);
        else        return p1 + ((size_t)((((b << 3) + (t - 8)) << 8) + s) << 9);
    } else {
        int b = r >> 4;
        int t = r & 15;
        if (t < 8)  return p0 + ((size_t)((b << 3) + t) << 9);
        else        return p1 + ((size_t)((b << 3) + (t - 8)) << 9);
    }
}

// ---------------------------------------------------------------------------
// Pre-conversion kernels
// ---------------------------------------------------------------------------
__global__ void __launch_bounds__(256) conv_tokens(
    const float* __restrict__ v_p, const float* __restrict__ v_f,
    const float* __restrict__ a_p, const float* __restrict__ a_f)
{
    int idx = blockIdx.x * 256 + threadIdx.x;    // one float4 per thread
    int row = idx >> 7;
    int c4  = (idx & 127) << 2;
    if (row >= MTOK) return;
    const float* src = (row < MV) ? token_ptr(row, 0, v_p, v_f)
                                  : token_ptr(row - MV, 1, a_p, a_f);
    float4 v = *(const float4*)(src + c4);
    __nv_bfloat16 h[4], l[4];
    cvt_hilo(v.x, h[0], l[0]); cvt_hilo(v.y, h[1], l[1]);
    cvt_hilo(v.z, h[2], l[2]); cvt_hilo(v.w, h[3], l[3]);
    size_t off = (size_t)row * D + c4;
    *(__nv_bfloat162*)(g_tok_hi + off)     = __nv_bfloat162(h[0], h[1]);
    *(__nv_bfloat162*)(g_tok_hi + off + 2) = __nv_bfloat162(h[2], h[3]);
    *(__nv_bfloat162*)(g_tok_lo + off)     = __nv_bfloat162(l[0], l[1]);
    *(__nv_bfloat162*)(g_tok_lo + off + 2) = __nv_bfloat162(l[2], l[3]);
}

__global__ void __launch_bounds__(256) conv_weights(
    const float* __restrict__ Wq, const float* __restrict__ Wp)
{
    int idx = blockIdx.x * 256 + threadIdx.x;    // one float4 per thread
    const int NQ4 = (D * NQKV) / 4;              // 196608
    const float* src;
    __nv_bfloat16 *dh, *dl;
    size_t off;
    if (idx < NQ4)      { src = Wq; dh = g_wq_hi; dl = g_wq_lo; off = (size_t)idx << 2; }
    else                { idx -= NQ4;
                          if (idx >= (D * D) / 4) return;
                          src = Wp; dh = g_wp_hi; dl = g_wp_lo; off = (size_t)idx << 2; }
    float4 v = *(const float4*)(src + off);
    __nv_bfloat16 h[4], l[4];
    cvt_hilo(v.x, h[0], l[0]); cvt_hilo(v.y, h[1], l[1]);
    cvt_hilo(v.z, h[2], l[2]); cvt_hilo(v.w, h[3], l[3]);
    *(__nv_bfloat162*)(dh + off)     = __nv_bfloat162(h[0], h[1]);
    *(__nv_bfloat162*)(dh + off + 2) = __nv_bfloat162(h[2], h[3]);
    *(__nv_bfloat162*)(dl + off)     = __nv_bfloat162(l[0], l[1]);
    *(__nv_bfloat162*)(dl + off + 2) = __nv_bfloat162(l[2], l[3]);
}

// RoPE sin/cos table + zero the a-mean staging
__global__ void rope_table_kernel(void)
{
    int idx = threadIdx.x + blockIdx.x * 256;
    if (idx < 1024) {
        int t = idx >> 5;
        int j = idx & 31;
        float inv = exp2f(-0.41524101186091903f * (float)j);
        float ang = (float)t * inv;
        float sn, cs;
        sincosf(ang, &sn, &cs);
        g_rope[idx] = make_float2(sn, cs);
    }
    if (idx < 64 * D) g_am[idx] = 0.f;
}

// ---------------------------------------------------------------------------
// Pipelined bf16x3 GEMM: 128x128 tile, BK=32, 2-stage cp.async, 256 threads.
// ---------------------------------------------------------------------------
#define STG_A_HI   0
#define STG_A_LO   10240
#define STG_B_HI   20480
#define STG_B_LO   29184
#define STG_STRIDE 37888
#define SMEM_BYTES (2 * STG_STRIDE)
#define NSLAB      16

__device__ __forceinline__ void prefetch_slab(
    uint32_t stg,
    const __nv_bfloat16* __restrict__ Ahi, const __nv_bfloat16* __restrict__ Alo,
    const __nv_bfloat16* __restrict__ Bhi, const __nv_bfloat16* __restrict__ Blo,
    int ldb, int bn, int k0, int tid)
{
    #pragma unroll
    for (int t = 0; t < 2; ++t) {
        int q  = tid + (t << 8);              // 0..511
        int r  = q >> 2, kc = (q & 3) << 3;   // A: 128 rows x 4 chunks
        uint32_t ao = (uint32_t)(r * 80 + (kc << 1));
        size_t asrc = (size_t)r * D + k0 + kc;
        CP16(stg + STG_A_HI + ao, Ahi + asrc);
        CP16(stg + STG_A_LO + ao, Alo + asrc);
        int br = q >> 4, nc = (q & 15) << 3;  // B: 32 rows x 16 chunks
        uint32_t bo = (uint32_t)(br * 272 + (nc << 1));
        size_t bsrc = (size_t)(k0 + br) * ldb + bn + nc;
        CP16(stg + STG_B_HI + bo, Bhi + bsrc);
        CP16(stg + STG_B_LO + bo, Blo + bsrc);
    }
}

__device__ __forceinline__ void compute_slab(
    char* stg, int m0, int n0, int lane, float (&acc)[2][8][4])
{
    uint32_t ah[2][4], al[2][4], bh[8][2], bl[8][2];
    #pragma unroll
    for (int ks = 0; ks < 2; ++ks) {
        const int k0   = ks << 4;
        const int arow = lane & 15;
        const int acol = k0 + ((lane >> 4) << 3);
        #pragma unroll
        for (int mt = 0; mt < 2; ++mt) {
            uint32_t ad = smem_u32(stg + STG_A_HI + (m0 + (mt << 4) + arow) * 80 + acol * 2);
            LDSM_X4(ah[mt][0], ah[mt][1], ah[mt][2], ah[mt][3], ad);
            uint32_t ad2 = smem_u32(stg + STG_A_LO + (m0 + (mt << 4) + arow) * 80 + acol * 2);
            LDSM_X4(al[mt][0], al[mt][1], al[mt][2], al[mt][3], ad2);
        }
        #pragma unroll
        for (int p = 0; p < 4; ++p) {
            const int ncol = n0 + (p << 4) + ((lane >> 4) << 3);
            uint32_t bd = smem_u32(stg + STG_B_HI + (k0 + (lane & 15)) * 272 + ncol * 2);
            LDSM_X4_T(bh[2*p][0], bh[2*p][1], bh[2*p+1][0], bh[2*p+1][1], bd);
            uint32_t bd2 = smem_u32(stg + STG_B_LO + (k0 + (lane & 15)) * 272 + ncol * 2);
            LDSM_X4_T(bl[2*p][0], bl[2*p][1], bl[2*p+1][0], bl[2*p+1][1], bd2);
        }
        #pragma unroll
        for (int mt = 0; mt < 2; ++mt)
            #pragma unroll
            for (int nt = 0; nt < 8; ++nt) {
                MMA16816(acc[mt][nt], ah[mt], bh[nt]);
                MMA16816(acc[mt][nt], ah[mt], bl[nt]);
                MMA16816(acc[mt][nt], al[mt], bh[nt]);
            }
    }
}

#define GEMM_MAIN(AHI, ALO, BHI, BLO, LDB, BN)                                   \
    extern __shared__ char smem[];                                               \
    const uint32_t sbase = smem_u32(smem);                                       \
    const int tid  = threadIdx.x;                                                \
    const int lane = tid & 31;                                                   \
    const int w    = tid >> 5;                                                   \
    const int m0   = (w >> 1) << 5;                                              \
    const int n0   = (w & 1) << 6;                                               \
    float acc[2][8][4];                                                          \
    _Pragma("unroll")                                                            \
    for (int mt = 0; mt < 2; ++mt)                                               \
        _Pragma("unroll")                                                        \
        for (int nt = 0; nt < 8; ++nt)                                           \
            _Pragma("unroll")                                                    \
            for (int e = 0; e < 4; ++e) acc[mt][nt][e] = 0.f;                    \
    prefetch_slab(sbase, AHI, ALO, BHI, BLO, LDB, BN, 0, tid);                   \
    CP_COMMIT();                                                                 \
    for (int ks = 0; ks < NSLAB; ++ks) {                                         \
        if (ks + 1 < NSLAB) {                                                    \
            prefetch_slab(sbase + ((ks + 1) & 1) * STG_STRIDE,                   \
                          AHI, ALO, BHI, BLO, LDB, BN, (ks + 1) * 32, tid);      \
            CP_COMMIT();                                                         \
            CP_WAIT(1);                                                          \
        } else {                                                                 \
            CP_WAIT(0);                                                          \
        }                                                                        \
        __syncthreads();                                                         \
        compute_slab(smem + (ks & 1) * STG_STRIDE, m0, n0, lane, acc);           \
        __syncthreads();                                                         \
    }

// ---------------------------------------------------------------------------
// QKV GEMM with fused RoPE + bf16 hi/lo split epilogue.
// ---------------------------------------------------------------------------
__global__ void __launch_bounds__(256) qkv_gemm(void)
{
    const int bm = blockIdx.y << 7;
    const int bn = blockIdx.x << 7;
    GEMM_MAIN(g_tok_hi + (size_t)bm * D, g_tok_lo + (size_t)bm * D,
              g_wq_hi, g_wq_lo, NQKV, bn)

    const int cw     = bn + n0;            // 64-aligned global col window
    const int region = cw >> 9;            // 0=Q, 1=K, 2=V
    __nv_bfloat16 *dh, *dl;
    if (region == 0)      { dh = g_q_hi; dl = g_q_lo; }
    else if (region == 1) { dh = g_k_hi; dl = g_k_lo; }
    else                  { dh = g_v_hi; dl = g_v_lo; }
    const int cbase = cw & 511;

    #pragma unroll
    for (int mt = 0; mt < 2; ++mt) {
        int rA   = bm + m0 + (mt << 4) + (lane >> 2);
        int posA = (rA & 15) + ((rA >= MV) ? 16 : 0);
        if (region < 2) {
            #pragma unroll
            for (int nt = 0; nt < 4; ++nt) {
                #pragma unroll
                for (int je = 0; je < 2; ++je) {
                    int j = (nt << 3) + ((lane & 3) << 1) + je;
                    float2 scA = g_rope[(posA << 5) + j];
                    float2 scB = g_rope[((posA + 8) << 5) + j];
                    float x1 = acc[mt][nt][je],   x2 = acc[mt][nt+4][je];
                    acc[mt][nt][je]     = x1 * scA.y - x2 * scA.x;
                    acc[mt][nt+4][je]   = x2 * scA.y + x1 * scA.x;
                    float y1 = acc[mt][nt][je+2], y2 = acc[mt][nt+4][je+2];
                    acc[mt][nt][je+2]   = y1 * scB.y - y2 * scB.x;
                    acc[mt][nt+4][je+2] = y2 * scB.y + y1 * scB.x;
                }
            }
        }
        #pragma unroll
        for (int nt = 0; nt < 8; ++nt) {
            int c = cbase + (nt << 3) + ((lane & 3) << 1);
            if (rA < MTOK) {
                __nv_bfloat16 h0,l0,h1,l1;
                cvt_hilo(acc[mt][nt][0], h0, l0);
                cvt_hilo(acc[mt][nt][1], h1, l1);
                *(__nv_bfloat162*)(dh + (size_t)rA * D + c) = __nv_bfloat162(h0, h1);
                *(__nv_bfloat162*)(dl + (size_t)rA * D + c) = __nv_bfloat162(l0, l1);
            }
            if (rA + 8 < MTOK) {
                __nv_bfloat16 h2,l2,h3,l3;
                cvt_hilo(acc[mt][nt][2], h2, l2);
                cvt_hilo(acc[mt][nt][3], h3, l3);
                *(__nv_bfloat162*)(dh + (size_t)(rA + 8) * D + c) = __nv_bfloat162(h2, h3);
                *(__nv_bfloat162*)(dl + (size_t)(rA + 8) * D + c) = __nv_bfloat162(l2, l3);
            }
        }
    }
}

// ---------------------------------------------------------------------------
// Proj GEMM: g_o2[16448,512] @ W_proj[512,512] + bias, scatter (NO atomics).
// ---------------------------------------------------------------------------
__device__ __forceinline__ void scatter2(float* __restrict__ out, int r, int c, float v)
{
    if (r < MV) {
        int bs = r >> 4, t = r & 15, b = bs >> 8, s = bs & 255;
        if (t < 8)
            out[((size_t)((((b << 3) + t) << 8) + s) << 9) + c] = v;
        else
            out[OFF1 + ((size_t)((((b << 3) + (t - 8)) << 8) + s) << 9) + c] = v;
    } else if (r < MTOK) {
        int j = r - MV;
        int b = j >> 4, tt = j & 15;
        if (tt < 8)
            out[OFF2 + (((b << 3) + tt) << 9) + c] = v;
        else
            out[OFF3 + (((b << 3) + (tt - 8)) << 9) + c] = v;
    }
}

__global__ void __launch_bounds__(256) proj_gemm(
    const float* __restrict__ bias, float* __restrict__ out)
{
    const int bm = blockIdx.y << 7;
    const int bn = blockIdx.x << 7;
    GEMM_MAIN(g_o2_hi + (size_t)bm * D, g_o2_lo + (size_t)bm * D,
              g_wp_hi, g_wp_lo, D, bn)

    #pragma unroll
    for (int mt = 0; mt < 2; ++mt) {
        int r0 = bm + m0 + (mt << 4) + (lane >> 2);
        #pragma unroll
        for (int nt = 0; nt < 8; ++nt) {
            int c = bn + n0 + (nt << 3) + ((lane & 3) << 1);
            float b0 = bias[c], b1 = bias[c + 1];
            scatter2(out, r0,     c,     acc[mt][nt][0] + b0);
            scatter2(out, r0,     c + 1, acc[mt][nt][1] + b1);
            scatter2(out, r0 + 8, c,     acc[mt][nt][2] + b0);
            scatter2(out, r0 + 8, c + 1, acc[mt][nt][3] + b1);
        }
    }
}

// ---------------------------------------------------------------------------
// a-row mean: partials (grid 64 x 8, 32 s each) -> fp32 atomics -> finalize
// ---------------------------------------------------------------------------
__global__ void __launch_bounds__(256) reduce_a(void)
{
    int j  = blockIdx.x;            // 0..63 = b*16+tt
    int sq = blockIdx.y;            // 0..7
    int c2 = threadIdx.x << 1;
    int b  = j >> 4;
    int tt = j & 15;
    float s0 = 0.f, s1 = 0.f;
    int sbase = sq << 5;
    #pragma unroll 4
    for (int s = 0; s < 32; ++s) {
        const float* row = g_oa + (size_t)((((b << 8) + sbase + s) << 4) + tt) * D + c2;
        float2 v = *(const float2*)row;
        s0 += v.x; s1 += v.y;
    }
    atomicAdd(&g_am[j * D + c2],     s0 * (1.f / 256.f));
    atomicAdd(&g_am[j * D + c2 + 1], s1 * (1.f / 256.f));
}

__global__ void __launch_bounds__(256) conv_am(void)
{
    int j  = blockIdx.x;
    int c2 = threadIdx.x << 1;
    float2 v = *(const float2*)(g_am + j * D + c2);
    __nv_bfloat16 h0, l0, h1, l1;
    cvt_hilo(v.x, h0, l0);
    cvt_hilo(v.y, h1, l1);
    size_t off = (size_t)(MV + j) * D + c2;
    *(__nv_bfloat162*)(g_o2_hi + off) = __nv_bfloat162(h0, h1);
    *(__nv_bfloat162*)(g_o2_lo + off) = __nv_bfloat162(l0, l1);
}

// ---------------------------------------------------------------------------
// Attention (tensor-core, pure-copy staging, KT-transposed K — R15 config):
// one block per (bs, head), 128 threads.
// Smem: QH/QL [32][72] @ 0/4608; KTH/KTL [64][40] @ 9216/14336;
//       VH/VL [32][72] @ 19456/24064; PH/PL [32][40] @ 28672/31232;
//       Ss [32][33] f32 @ 33792. Total 38016.
// ---------------------------------------------------------------------------
#define A_QH  0
#define A_QL  4608
#define A_KTH 9216
#define A_KTL 14336
#define A_VH  19456
#define A_VL  24064
#define A_PH  28672
#define A_PL  31232
#define A_SS  33792
#define ATT_SMEM 38016

__global__ void __launch_bounds__(128) attn_kernel()
{
    extern __shared__ char asm_[];
    __nv_bfloat16* QH = (__nv_bfloat16*)(asm_ + A_QH);   // [32][72]
    __nv_bfloat16* QL = (__nv_bfloat16*)(asm_ + A_QL);
    __nv_bfloat16* KTH = (__nv_bfloat16*)(asm_ + A_KTH); // [64][40]
    __nv_bfloat16* KTL = (__nv_bfloat16*)(asm_ + A_KTL);
    __nv_bfloat16* VH = (__nv_bfloat16*)(asm_ + A_VH);   // [32][72]
    __nv_bfloat16* VL = (__nv_bfloat16*)(asm_ + A_VL);
    __nv_bfloat16* PH = (__nv_bfloat16*)(asm_ + A_PH);   // [32][40]
    __nv_bfloat16* PL = (__nv_bfloat16*)(asm_ + A_PL);
    float* Ss = (float*)(asm_ + A_SS);                   // [32][33]

    const int tid  = threadIdx.x;
    const int lane = tid & 31;
    const int w    = tid >> 5;
    const int bh   = blockIdx.x;
    const int bs   = bh >> 3;
    const int h    = bh & 7;
    const int b    = bs >> 8;

    // Phase 1: pure copy staging (Q/V row-major 16B, K transposed scalar)
    #pragma unroll
    for (int p = 0; p < 2; ++p) {
        int idx = tid + (p << 7);         // 0..255
        int t   = idx >> 3;               // 0..31 row
        int c8  = (idx & 7) << 3;         // 0,8,..,56
        int row = (t < 16) ? ((bs << 4) + t) : (MV + (b << 4) + (t - 16));
        size_t src = (size_t)row * D + (h << 6) + c8;
        uint4 qh = *(const uint4*)(g_q_hi + src);
        uint4 ql = *(const uint4*)(g_q_lo + src);
        uint4 kh = *(const uint4*)(g_k_hi + src);
        uint4 kl = *(const uint4*)(g_k_lo + src);
        uint4 vh = *(const uint4*)(g_v_hi + src);
        uint4 vl = *(const uint4*)(g_v_lo + src);
        *(uint4*)(QH + t*72 + c8) = qh;
        *(uint4*)(QL + t*72 + c8) = ql;
        *(uint4*)(VH + t*72 + c8) = vh;
        *(uint4*)(VL + t*72 + c8) = vl;
        const __nv_bfloat16* pkh = (const __nv_bfloat16*)&kh;
        const __nv_bfloat16* pkl = (const __nv_bfloat16*)&kl;
        #pragma unroll
        for (int e = 0; e < 8; ++e) {
            KTH[(c8 + e)*40 + t] = pkh[e];
            KTL[(c8 + e)*40 + t] = pkl[e];
        }
    }
    __syncthreads();

    // Phase 2: S = QK^T * scale via MMA. Warp w: m0=(w&1)*16, n0=(w>>1)*16.
    {
        const int m0 = (w & 1) << 4;
        const int n0 = (w >> 1) << 4;
        float sacc[2][4] = {{0.f,0.f,0.f,0.f},{0.f,0.f,0.f,0.f}};
        uint32_t ah[4], al[4], bhf[2][2], blf[2][2];
        #pragma unroll
        for (int kc = 0; kc < 4; ++kc) {
            const int k0 = kc << 4;
            const int arow = m0 + (lane & 15);
            const int acol = k0 + ((lane >> 4) << 3);
            LDSM_X4(ah[0], ah[1], ah[2], ah[3], smem_u32(QH + arow*72 + acol));
            LDSM_X4(al[0], al[1], al[2], al[3], smem_u32(QL + arow*72 + acol));
            const int brow = k0 + (lane & 15);
            const int bcol = n0 + ((lane >> 4) << 3);
            LDSM_X4_T(bhf[0][0], bhf[0][1], bhf[1][0], bhf[1][1], smem_u32(KTH + brow*40 + bcol));
            LDSM_X4_T(blf[0][0], blf[0][1], blf[1][0], blf[1][1], smem_u32(KTL + brow*40 + bcol));
            #pragma unroll
            for (int nt = 0; nt < 2; ++nt) {
                MMA16816(sacc[nt], ah, bhf[nt]);
                MMA16816(sacc[nt], ah, blf[nt]);
                MMA16816(sacc[nt], al, bhf[nt]);
            }
        }
        const int r0 = m0 + (lane >> 2);
        #pragma unroll
        for (int nt = 0; nt < 2; ++nt) {
            int c = n0 + (nt << 3) + ((lane & 3) << 1);
            Ss[r0*33 + c]       = sacc[nt][0] * 0.125f;
            Ss[r0*33 + c + 1]   = sacc[nt][1] * 0.125f;
            Ss[(r0+8)*33 + c]     = sacc[nt][2] * 0.125f;
            Ss[(r0+8)*33 + c + 1] = sacc[nt][3] * 0.125f;
        }
    }
    __syncthreads();

    // Phase 3: row softmax; emit P as bf16 hi/lo directly
    #pragma unroll
    for (int rr = 0; rr < 8; ++rr) {
        int i = (w << 3) + rr;
        float val = Ss[i*33 + lane];
        float m = val;
        #pragma unroll
        for (int o = 16; o > 0; o >>= 1) m = fmaxf(m, __shfl_xor_sync(0xffffffffu, m, o));
        float e = expf(val - m);
        float sum = e;
        #pragma unroll
        for (int o = 16; o > 0; o >>= 1) sum += __shfl_xor_sync(0xffffffffu, sum, o);
        float pv = e / sum;
        __nv_bfloat16 hh, ll;
        cvt_hilo(pv, hh, ll);
        PH[i*40 + lane] = hh;
        PL[i*40 + lane] = ll;
    }
    __syncthreads();

    // Phase 4: O = P @ V via MMA. Warp w: m0=(w&1)*16, n0=(w>>1)*32.
    {
        const int m0 = (w & 1) << 4;
        const int n0 = (w >> 1) << 5;
        float oacc[4][4];
        #pragma unroll
        for (int nt = 0; nt < 4; ++nt)
            #pragma unroll
            for (int e = 0; e < 4; ++e) oacc[nt][e] = 0.f;
        uint32_t ah[4], al[4], bhf[4][2], blf[4][2];
        #pragma unroll
        for (int kc = 0; kc < 2; ++kc) {
            const int k0 = kc << 4;
            const int arow = m0 + (lane & 15);
            const int acol = k0 + ((lane >> 4) << 3);
            LDSM_X4(ah[0], ah[1], ah[2], ah[3], smem_u32(PH + arow*40 + acol));
            LDSM_X4(al[0], al[1], al[2], al[3], smem_u32(PL + arow*40 + acol));
            #pragma unroll
            for (int p = 0; p < 2; ++p) {
                const int brow = k0 + (lane & 15);
                const int bcol = n0 + (p << 4) + ((lane >> 4) << 3);
                LDSM_X4_T(bhf[2*p][0], bhf[2*p][1], bhf[2*p+1][0], bhf[2*p+1][1],
                          smem_u32(VH + brow*72 + bcol));
                LDSM_X4_T(blf[2*p][0], blf[2*p][1], blf[2*p+1][0], blf[2*p+1][1],
                          smem_u32(VL + brow*72 + bcol));
            }
            #pragma unroll
            for (int nt = 0; nt < 4; ++nt) {
                MMA16816(oacc[nt], ah, bhf[nt]);
                MMA16816(oacc[nt], ah, blf[nt]);
                MMA16816(oacc[nt], al, bhf[nt]);
            }
        }
        // Epilogue: m0==0 -> v rows (bf16 hi/lo to g_o2); m0==16 -> a rows (fp32)
        const int r0 = m0 + (lane >> 2);
        if (m0 == 0) {
            #pragma unroll
            for (int nt = 0; nt < 4; ++nt) {
                int c = n0 + (nt << 3) + ((lane & 3) << 1);
                size_t o0 = (size_t)((bs << 4) + r0) * D + (h << 6) + c;
                size_t o1 = (size_t)((bs << 4) + r0 + 8) * D + (h << 6) + c;
                __nv_bfloat16 h0,l0,h1,l1,h2,l2,h3,l3;
                cvt_hilo(oacc[nt][0], h0, l0); cvt_hilo(oacc[nt][1], h1, l1);
                cvt_hilo(oacc[nt][2], h2, l2); cvt_hilo(oacc[nt][3], h3, l3);
                *(__nv_bfloat162*)(g_o2_hi + o0) = __nv_bfloat162(h0, h1);
                *(__nv_bfloat162*)(g_o2_lo + o0) = __nv_bfloat162(l0, l1);
                *(__nv_bfloat162*)(g_o2_hi + o1) = __nv_bfloat162(h2, h3);
                *(__nv_bfloat162*)(g_o2_lo + o1) = __nv_bfloat162(l2, l3);
            }
        } else {
            int ra = r0 - 16;                 // 0..7
            #pragma unroll
            for (int nt = 0; nt < 4; ++nt) {
                int c = n0 + (nt << 3) + ((lane & 3) << 1);
                size_t o0 = (size_t)((bs << 4) + ra) * D + (h << 6) + c;
                size_t o1 = (size_t)((bs << 4) + ra + 8) * D + (h << 6) + c;
                *(float2*)(g_oa + o0) = make_float2(oacc[nt][0], oacc[nt][1]);
                *(float2*)(g_oa + o1) = make_float2(oacc[nt][2], oacc[nt][3]);
            }
        }
    }
}

// ---------------------------------------------------------------------------
extern "C" void kernel_launch(void* const* d_in, const int* in_sizes, int n_in,
                              void* d_out, int out_size)
{
    const float* v_p    = (const float*)d_in[0];
    const float* v_f    = (const float*)d_in[1];
    const float* a_p    = (const float*)d_in[2];
    const float* a_f    = (const float*)d_in[3];
    const float* W_qkv  = (const float*)d_in[4];
    const float* W_proj = (const float*)d_in[5];
    const float* b_proj = (const float*)d_in[6];
    float* out = (float*)d_out;

    cudaFuncSetAttribute(qkv_gemm,  cudaFuncAttributeMaxDynamicSharedMemorySize, SMEM_BYTES);
    cudaFuncSetAttribute(proj_gemm, cudaFuncAttributeMaxDynamicSharedMemorySize, SMEM_BYTES);
    cudaFuncSetAttribute(attn_kernel, cudaFuncAttributeMaxDynamicSharedMemorySize, ATT_SMEM);

    rope_table_kernel<<<128, 256>>>();       // rope table + zero g_am
    conv_weights<<<1024, 256>>>(W_qkv, W_proj);
    conv_tokens<<<8224, 256>>>(v_p, v_f, a_p, a_f);

    qkv_gemm<<<dim3(12, 129), 256, SMEM_BYTES>>>();

    attn_kernel<<<8192, 128, ATT_SMEM>>>();

    reduce_a<<<dim3(64, 8), 256>>>();
    conv_am<<<64, 256>>>();

    proj_gemm<<<dim3(4, 129), 256, SMEM_BYTES>>>(b_proj, out);
}